// round 5
// baseline (speedup 1.0000x reference)
#include <cuda_runtime.h>
#include <cuda_fp16.h>
#include <stdint.h>

namespace {

constexpr int M  = 32;
constexpr int N  = 11008;
constexpr int K  = 4096;
constexpr int NT = 64;                 // output channels per CTA
constexpr int KC = 64;                 // K elems per stage
constexpr int NITER  = K / KC;         // 64
constexpr int STAGES = 4;
constexpr int SW = 68;                 // padded row stride in 4B words (64 + 4)
constexpr int W_WORDS = NT * SW;       // 4352
constexpr int X_WORDS = M * SW;        // 2176
constexpr int STAGE_WORDS = W_WORDS + X_WORDS;     // 6528
constexpr int SMEM_BYTES  = STAGES * STAGE_WORDS * 4;  // 104448

__device__ __forceinline__ void cp16(uint32_t dst, const void* src) {
    asm volatile("cp.async.cg.shared.global [%0], [%1], 16;\n" :: "r"(dst), "l"(src));
}
__device__ __forceinline__ void cp_commit() {
    asm volatile("cp.async.commit_group;\n");
}
template <int Ngrp> __device__ __forceinline__ void cp_wait() {
    asm volatile("cp.async.wait_group %0;\n" :: "n"(Ngrp));
}

__device__ __forceinline__ void mma16816(float c[4], const uint32_t a[4], const uint32_t b[2]) {
    asm volatile(
        "mma.sync.aligned.m16n8k16.row.col.f32.f16.f16.f32 "
        "{%0,%1,%2,%3}, {%4,%5,%6,%7}, {%8,%9}, {%0,%1,%2,%3};"
        : "+f"(c[0]), "+f"(c[1]), "+f"(c[2]), "+f"(c[3])
        : "r"(a[0]), "r"(a[1]), "r"(a[2]), "r"(a[3]), "r"(b[0]), "r"(b[1]));
}

__device__ __forceinline__ uint32_t pack_f2(float2 f) {
    __half2 h = __floats2half2_rn(f.x, f.y);
    return *reinterpret_cast<uint32_t*>(&h);
}
__device__ __forceinline__ uint32_t pack_i2(int2 v) {
    __half2 h = __halves2half2(__int2half_rn(v.x), __int2half_rn(v.y));
    return *reinterpret_cast<uint32_t*>(&h);
}

__global__ void __launch_bounds__(256, 2)
qlinear_kernel(const float* __restrict__ x, const uint32_t* __restrict__ qw,
               const float* __restrict__ scales, const float* __restrict__ bias,
               float* __restrict__ out)
{
    extern __shared__ uint32_t sm[];
    const uint32_t sm_u32 = (uint32_t)__cvta_generic_to_shared(sm);

    const int tid  = threadIdx.x;
    const int lane = tid & 31;
    const int warp = tid >> 5;
    const int wn   = warp & 3;     // n16 slot of the 64-wide tile
    const int kg   = warp >> 2;    // k-half of each staged chunk
    const int o0   = blockIdx.x * NT;

    // ---- uniform dtype probe on qweight words: 0 = int32, 1 = float32 ----
    int mode;
    {
        uint32_t all_int = 1u;
#pragma unroll
        for (int i = 0; i < 8; ++i) {
            uint32_t w = __ldg(qw + i);
            all_int &= ((w + 128u) < 256u) ? 1u : 0u;
        }
        mode = all_int ? 0 : 1;
    }

    // ---- producer: cp.async raw int32/f32 tiles into the stage ring ----
    auto issue = [&](int it) {
        const int buf = it % STAGES;
        const int kc  = it * KC;
        const uint32_t wdst = sm_u32 + buf * (STAGE_WORDS * 4);
        const uint32_t xdst = wdst + W_WORDS * 4;
#pragma unroll
        for (int p = 0; p < 4; ++p) {              // 1024 16B chunks: 64 rows x 16
            int g = p * 256 + tid;
            int row = g >> 4, c16 = g & 15;
            cp16(wdst + row * (SW * 4) + c16 * 16,
                 qw + (size_t)(o0 + row) * K + kc + c16 * 4);
        }
#pragma unroll
        for (int p = 0; p < 2; ++p) {              // 512 16B chunks: 32 rows x 16
            int g = p * 256 + tid;
            int row = g >> 4, c16 = g & 15;
            cp16(xdst + row * (SW * 4) + c16 * 16,
                 x + (size_t)row * K + kc + c16 * 4);
        }
    };

    float acc[2][2][4];
#pragma unroll
    for (int i = 0; i < 2; ++i)
#pragma unroll
        for (int j = 0; j < 2; ++j)
#pragma unroll
            for (int e = 0; e < 4; ++e) acc[i][j][e] = 0.f;

    // ---- consumer: direct LDS in mma fragment layout + in-register convert ----
    const int fr = lane >> 2;          // fragment row/col group
    const int fk = (lane & 3) * 2;     // fragment k pair base

    auto compute = [&](int it) {
        const int buf = it % STAGES;
        const uint32_t* wb = sm + buf * STAGE_WORDS;
        const float*    xb = reinterpret_cast<const float*>(sm + buf * STAGE_WORDS + W_WORDS);
#pragma unroll
        for (int tt = 0; tt < 2; ++tt) {
            const int c = kg * 32 + tt * 16 + fk;

            uint32_t a[2][4];
#pragma unroll
            for (int mt = 0; mt < 2; ++mt) {
                const float* xr0 = xb + (mt * 16 + fr) * SW;
                const float* xr8 = xb + (mt * 16 + fr + 8) * SW;
                a[mt][0] = pack_f2(*reinterpret_cast<const float2*>(xr0 + c));
                a[mt][1] = pack_f2(*reinterpret_cast<const float2*>(xr8 + c));
                a[mt][2] = pack_f2(*reinterpret_cast<const float2*>(xr0 + c + 8));
                a[mt][3] = pack_f2(*reinterpret_cast<const float2*>(xr8 + c + 8));
            }
#pragma unroll
            for (int nf = 0; nf < 2; ++nf) {
                const uint32_t* wr = wb + (wn * 16 + nf * 8 + fr) * SW;
                uint32_t b[2];
                if (mode == 0) {
                    b[0] = pack_i2(*reinterpret_cast<const int2*>(wr + c));
                    b[1] = pack_i2(*reinterpret_cast<const int2*>(wr + c + 8));
                } else {
                    const float* wf = reinterpret_cast<const float*>(wr);
                    b[0] = pack_f2(*reinterpret_cast<const float2*>(wf + c));
                    b[1] = pack_f2(*reinterpret_cast<const float2*>(wf + c + 8));
                }
                mma16816(acc[0][nf], a[0], b);
                mma16816(acc[1][nf], a[1], b);
            }
        }
    };

    // ---- multistage mainloop ----
#pragma unroll
    for (int s = 0; s < STAGES - 1; ++s) { issue(s); cp_commit(); }

    for (int it = 0; it < NITER; ++it) {
        if (it + STAGES - 1 < NITER) issue(it + STAGES - 1);
        cp_commit();
        cp_wait<STAGES - 1>();   // stage `it` landed
        __syncthreads();         // ...for every thread's chunks
        compute(it);
        __syncthreads();         // buffer free before (it+STAGES) overwrites it
    }

    // ---- split-K reduction across kg halves ----
    float* red = reinterpret_cast<float*>(sm);   // 8 KB scratch, ring is dead
    if (kg == 1) {
#pragma unroll
        for (int i = 0; i < 2; ++i)
#pragma unroll
            for (int j = 0; j < 2; ++j)
#pragma unroll
                for (int e = 0; e < 4; ++e)
                    red[((wn * 32 + lane) * 16) + (i * 2 + j) * 4 + e] = acc[i][j][e];
    }
    __syncthreads();
    if (kg == 0) {
#pragma unroll
        for (int i = 0; i < 2; ++i)
#pragma unroll
            for (int j = 0; j < 2; ++j)
#pragma unroll
                for (int e = 0; e < 4; ++e)
                    acc[i][j][e] += red[((wn * 32 + lane) * 16) + (i * 2 + j) * 4 + e];

        // ---- epilogue: scale + bias (f32), round to fp16 values, store f32 ----
        const int gm = lane >> 2;
        const int gn = (lane & 3) * 2;
#pragma unroll
        for (int nt = 0; nt < 2; ++nt) {
            const int o = o0 + wn * 16 + nt * 8 + gn;
            const float s0 = scales[o];
            const float s1 = scales[o + 1];
            const float b0 = bias[o];
            const float b1 = bias[o + 1];
#pragma unroll
            for (int mt = 0; mt < 2; ++mt) {
                const float* c = acc[mt][nt];
                const int r0 = mt * 16 + gm;
                float2 v0, v1;
                v0.x = __half2float(__float2half_rn(c[0] * s0 + b0));
                v0.y = __half2float(__float2half_rn(c[1] * s1 + b1));
                v1.x = __half2float(__float2half_rn(c[2] * s0 + b0));
                v1.y = __half2float(__float2half_rn(c[3] * s1 + b1));
                *reinterpret_cast<float2*>(out + (size_t)r0 * N + o) = v0;
                *reinterpret_cast<float2*>(out + (size_t)(r0 + 8) * N + o) = v1;
            }
        }
    }
}

} // anonymous namespace

extern "C" void kernel_launch(void* const* d_in, const int* in_sizes, int n_in,
                              void* d_out, int out_size) {
    const float*    x  = reinterpret_cast<const float*>(d_in[0]);
    const uint32_t* qw = reinterpret_cast<const uint32_t*>(d_in[1]);
    const float*    sc = reinterpret_cast<const float*>(d_in[2]);
    const float*    bi = reinterpret_cast<const float*>(d_in[3]);
    float*          o  = reinterpret_cast<float*>(d_out);

    cudaFuncSetAttribute(qlinear_kernel,
                         cudaFuncAttributeMaxDynamicSharedMemorySize, SMEM_BYTES);
    qlinear_kernel<<<N / NT, 256, SMEM_BYTES>>>(x, qw, sc, bi, o);
}

// round 6
// speedup vs baseline: 1.8246x; 1.8246x over previous
#include <cuda_runtime.h>
#include <cuda_fp16.h>
#include <stdint.h>

namespace {

constexpr int M  = 32;
constexpr int N  = 11008;
constexpr int K  = 4096;
constexpr int NT = 64;               // output channels per CTA
constexpr int KC = 64;               // K elems per stage
constexpr int NITER = K / KC;        // 64 (even -> paired loop is exact)
constexpr int WT_STRIDE = KC + 8;    // 72 halves = 144B rows (9x16B): conflict-free ldmatrix
constexpr int WT_HALVES = NT * WT_STRIDE;          // 4608
constexpr int XT_HALVES = M  * WT_STRIDE;          // 2304
constexpr int BUF_HALVES = WT_HALVES + XT_HALVES;  // 6912
constexpr int SMEM_BYTES = 2 * BUF_HALVES * 2;     // 27648

__device__ __forceinline__ void ldsm4(uint32_t r[4], uint32_t a) {
    asm volatile("ldmatrix.sync.aligned.m8n8.x4.shared.b16 {%0,%1,%2,%3}, [%4];"
                 : "=r"(r[0]), "=r"(r[1]), "=r"(r[2]), "=r"(r[3]) : "r"(a));
}
__device__ __forceinline__ void ldsm2(uint32_t r[2], uint32_t a) {
    asm volatile("ldmatrix.sync.aligned.m8n8.x2.shared.b16 {%0,%1}, [%2];"
                 : "=r"(r[0]), "=r"(r[1]) : "r"(a));
}
__device__ __forceinline__ void mma16816(float c[4], const uint32_t a[4], const uint32_t b[2]) {
    asm volatile(
        "mma.sync.aligned.m16n8k16.row.col.f32.f16.f16.f32 "
        "{%0,%1,%2,%3}, {%4,%5,%6,%7}, {%8,%9}, {%0,%1,%2,%3};"
        : "+f"(c[0]), "+f"(c[1]), "+f"(c[2]), "+f"(c[3])
        : "r"(a[0]), "r"(a[1]), "r"(a[2]), "r"(a[3]), "r"(b[0]), "r"(b[1]));
}
__device__ __forceinline__ uint32_t h2_u32(__half2 h) {
    return *reinterpret_cast<uint32_t*>(&h);
}

struct Sets {
    uint4 w[4];   // 64 weight words (this thread's share of a KC=64 x 64-row tile)
    uint4 xv[2];  // 32 x words
};

__global__ void __launch_bounds__(256, 2)
qlinear_kernel(const float* __restrict__ x, const uint32_t* __restrict__ qw,
               const float* __restrict__ scales, const float* __restrict__ bias,
               float* __restrict__ out)
{
    extern __shared__ __half sm[];

    const int tid  = threadIdx.x;
    const int lane = tid & 31;
    const int warp = tid >> 5;
    const int wn   = warp & 3;   // n16 slot within the 64-wide tile
    const int kg   = warp >> 2;  // k-half of each staged chunk
    const int o0   = blockIdx.x * NT;

    // ---- uniform dtype probe on qweight words: 0 = int32, 1 = float32 ----
    int mode;
    {
        uint32_t all_int = 1u;
#pragma unroll
        for (int i = 0; i < 8; ++i) {
            uint32_t w = __ldg(qw + i);
            all_int &= ((w + 128u) < 256u) ? 1u : 0u;
        }
        mode = all_int ? 0 : 1;
    }

    // per-thread granule mapping (fixed across iterations)
    //  weights: 1024 16B-chunks = 64 rows x 16;  x: 512 chunks = 32 rows x 16
    const int wrow0 = tid >> 4;          // +p*16 rows per step (256 threads / 16 chunks)
    const int c16   = tid & 15;
    const uint32_t* wsrc_base = qw + (size_t)(o0 + wrow0) * K + c16 * 4;
    const float*    xsrc_base = x  + (size_t)(tid >> 4) * K + c16 * 4;

    Sets setA, setB;  // register staging, parity-alternated

    auto ldg = [&](Sets& s, int it) {
        const int kc = it * KC;
#pragma unroll
        for (int p = 0; p < 4; ++p)
            s.w[p] = *reinterpret_cast<const uint4*>(wsrc_base + (size_t)(p * 16) * K + kc);
#pragma unroll
        for (int p = 0; p < 2; ++p)
            s.xv[p] = *reinterpret_cast<const uint4*>(xsrc_base + (size_t)(p * 16) * K + kc);
    };

    auto sts = [&](const Sets& s, __half* wt) {
        __half* xt = wt + WT_HALVES;
#pragma unroll
        for (int p = 0; p < 4; ++p) {
            float f0, f1, f2, f3;
            if (mode == 0) {
                f0 = (float)(int)s.w[p].x; f1 = (float)(int)s.w[p].y;
                f2 = (float)(int)s.w[p].z; f3 = (float)(int)s.w[p].w;
            } else {
                f0 = __uint_as_float(s.w[p].x); f1 = __uint_as_float(s.w[p].y);
                f2 = __uint_as_float(s.w[p].z); f3 = __uint_as_float(s.w[p].w);
            }
            uint32_t h01 = h2_u32(__floats2half2_rn(f0, f1));
            uint32_t h23 = h2_u32(__floats2half2_rn(f2, f3));
            *reinterpret_cast<uint2*>(
                reinterpret_cast<uint8_t*>(wt)
                + (wrow0 + p * 16) * (WT_STRIDE * 2) + c16 * 8) = make_uint2(h01, h23);
        }
#pragma unroll
        for (int p = 0; p < 2; ++p) {
            float f0 = __uint_as_float(s.xv[p].x), f1 = __uint_as_float(s.xv[p].y);
            float f2 = __uint_as_float(s.xv[p].z), f3 = __uint_as_float(s.xv[p].w);
            uint32_t h01 = h2_u32(__floats2half2_rn(f0, f1));
            uint32_t h23 = h2_u32(__floats2half2_rn(f2, f3));
            *reinterpret_cast<uint2*>(
                reinterpret_cast<uint8_t*>(xt)
                + (wrow0 + p * 16) * (WT_STRIDE * 2) + c16 * 8) = make_uint2(h01, h23);
        }
    };

    // ldmatrix lane->address maps (byte offsets within tiles)
    const int rowA  = ((lane >> 3) & 1) * 8 + (lane & 7);
    const int colA  = (lane >> 4) * 8;
    const int laneB = lane & 15;
    const int rowB  = laneB & 7;
    const int colB  = (laneB >> 3) * 8;
    const uint32_t aoff0 = ((0 + rowA) * WT_STRIDE + colA) * 2;
    const uint32_t aoff1 = ((16 + rowA) * WT_STRIDE + colA) * 2;
    const uint32_t boff0 = ((wn * 16 + 0 + rowB) * WT_STRIDE + colB) * 2;
    const uint32_t boff1 = ((wn * 16 + 8 + rowB) * WT_STRIDE + colB) * 2;

    float acc[2][2][4];
#pragma unroll
    for (int i = 0; i < 2; ++i)
#pragma unroll
        for (int j = 0; j < 2; ++j)
#pragma unroll
            for (int e = 0; e < 4; ++e) acc[i][j][e] = 0.f;

    __half* buf0 = sm;
    __half* buf1 = sm + BUF_HALVES;
    const uint32_t w0 = (uint32_t)__cvta_generic_to_shared(buf0);
    const uint32_t x0 = w0 + WT_HALVES * 2;
    const uint32_t w1 = (uint32_t)__cvta_generic_to_shared(buf1);
    const uint32_t x1 = w1 + WT_HALVES * 2;

    auto compute = [&](uint32_t wbase, uint32_t xbase) {
#pragma unroll
        for (int s = 0; s < 2; ++s) {
            const uint32_t koff = (uint32_t)(kg * 32 + s * 16) * 2;
            uint32_t a0[4], a1[4], bf0[2], bf1[2];
            ldsm4(a0, xbase + aoff0 + koff);
            ldsm4(a1, xbase + aoff1 + koff);
            ldsm2(bf0, wbase + boff0 + koff);
            ldsm2(bf1, wbase + boff1 + koff);
            mma16816(acc[0][0], a0, bf0);
            mma16816(acc[0][1], a0, bf1);
            mma16816(acc[1][0], a1, bf0);
            mma16816(acc[1][1], a1, bf1);
        }
    };

    // ---- prologue: stage 0 -> smem buf0; stage 1 staged in setB regs ----
    ldg(setA, 0);
    sts(setA, buf0);
    ldg(setB, 1);
    __syncthreads();

    // ---- mainloop, distance-2 register prefetch, parity-unrolled ----
    for (int it2 = 0; it2 < NITER; it2 += 2) {
        // even iteration: compute buf0, drain setB -> buf1, refill setA
        if (it2 + 2 < NITER) ldg(setA, it2 + 2);
        compute(w0, x0);
        sts(setB, buf1);                     // it2+1 <= NITER-1 always
        __syncthreads();

        // odd iteration: compute buf1, drain setA -> buf0, refill setB
        if (it2 + 3 < NITER) ldg(setB, it2 + 3);
        compute(w1, x1);
        if (it2 + 2 < NITER) sts(setA, buf0);
        __syncthreads();
    }

    // ---- split-K reduction across kg halves ----
    float* red = reinterpret_cast<float*>(sm);   // 8 KB scratch, buffers dead
    if (kg == 1) {
#pragma unroll
        for (int i = 0; i < 2; ++i)
#pragma unroll
            for (int j = 0; j < 2; ++j)
#pragma unroll
                for (int e = 0; e < 4; ++e)
                    red[((wn * 32 + lane) * 16) + (i * 2 + j) * 4 + e] = acc[i][j][e];
    }
    __syncthreads();
    if (kg == 0) {
#pragma unroll
        for (int i = 0; i < 2; ++i)
#pragma unroll
            for (int j = 0; j < 2; ++j)
#pragma unroll
                for (int e = 0; e < 4; ++e)
                    acc[i][j][e] += red[((wn * 32 + lane) * 16) + (i * 2 + j) * 4 + e];

        // ---- epilogue: scale + bias (f32), round to fp16 values, store f32 ----
        const int gm = lane >> 2;
        const int gn = (lane & 3) * 2;
#pragma unroll
        for (int nt = 0; nt < 2; ++nt) {
            const int o = o0 + wn * 16 + nt * 8 + gn;
            const float s0 = scales[o];
            const float s1 = scales[o + 1];
            const float b0 = bias[o];
            const float b1 = bias[o + 1];
#pragma unroll
            for (int mt = 0; mt < 2; ++mt) {
                const float* c = acc[mt][nt];
                const int r0 = mt * 16 + gm;
                float2 v0, v1;
                v0.x = __half2float(__float2half_rn(c[0] * s0 + b0));
                v0.y = __half2float(__float2half_rn(c[1] * s1 + b1));
                v1.x = __half2float(__float2half_rn(c[2] * s0 + b0));
                v1.y = __half2float(__float2half_rn(c[3] * s1 + b1));
                *reinterpret_cast<float2*>(out + (size_t)r0 * N + o) = v0;
                *reinterpret_cast<float2*>(out + (size_t)(r0 + 8) * N + o) = v1;
            }
        }
    }
}

} // anonymous namespace

extern "C" void kernel_launch(void* const* d_in, const int* in_sizes, int n_in,
                              void* d_out, int out_size) {
    const float*    x  = reinterpret_cast<const float*>(d_in[0]);
    const uint32_t* qw = reinterpret_cast<const uint32_t*>(d_in[1]);
    const float*    sc = reinterpret_cast<const float*>(d_in[2]);
    const float*    bi = reinterpret_cast<const float*>(d_in[3]);
    float*          o  = reinterpret_cast<float*>(d_out);

    cudaFuncSetAttribute(qlinear_kernel,
                         cudaFuncAttributeMaxDynamicSharedMemorySize, SMEM_BYTES);
    qlinear_kernel<<<N / NT, 256, SMEM_BYTES>>>(x, qw, sc, bi, o);
}